// round 11
// baseline (speedup 1.0000x reference)
#include <cuda_runtime.h>
#include <math.h>

// Problem constants
#define U 64
#define M 8192
#define D 64
#define CHUNKS 8                        // 8 chunks x 64 units = 512 blocks (1 wave)
#define SLOTS_PER_CHUNK (M / CHUNKS)    // 1024

// Fused pipeline: 32 slots/stage; att 8 KB + mem 8 KB per stage; 3 stages
#define STAGE_SLOTS 32
#define ATT_STAGE_BYTES (STAGE_SLOTS * D * 4)     // 8192
#define MEM_STAGE_BYTES (STAGE_SLOTS * D * 4)     // 8192
#define NSTAGES 3
#define NITERS (SLOTS_PER_CHUNK / STAGE_SLOTS)    // 32

// Output layout (float32, tuple concatenated):
//   outputs  [64,64]      at 0
//   weights  [64,8192]    at 4096
//   memories [64,8192,64] at 528384
#define OFF_OUTPUTS  0
#define OFF_WEIGHTS  (U * D)
#define OFF_MEMCOPY  (U * D + U * M)

// Scratch (device globals; no allocation, no cross-block sync needed)
__device__ float2 g_stats[U * CHUNKS];           // per-(unit,chunk) (max, sumexp)
__device__ float  g_partial[U * CHUNKS * D];     // per-(unit,chunk) partial outputs

// ---------------------------------------------------------------------------
// mbarrier / bulk-async helpers
// ---------------------------------------------------------------------------
__device__ __forceinline__ unsigned smem_u32(const void* p) {
    return (unsigned)__cvta_generic_to_shared(p);
}
__device__ __forceinline__ void mbar_init(unsigned a, unsigned cnt) {
    asm volatile("mbarrier.init.shared.b64 [%0], %1;" :: "r"(a), "r"(cnt) : "memory");
}
__device__ __forceinline__ void mbar_expect_tx(unsigned a, unsigned bytes) {
    asm volatile("mbarrier.arrive.expect_tx.shared.b64 _, [%0], %1;"
                 :: "r"(a), "r"(bytes) : "memory");
}
__device__ __forceinline__ void mbar_wait(unsigned a, unsigned parity) {
    asm volatile(
        "{\n\t.reg .pred p;\n\t"
        "WL_%=:\n\t"
        "mbarrier.try_wait.parity.acquire.cta.shared::cta.b64 p, [%0], %1, 0x989680;\n\t"
        "@!p bra WL_%=;\n\t}"
        :: "r"(a), "r"(parity) : "memory");
}
__device__ __forceinline__ void bulk_load(unsigned dst_smem, const void* src,
                                          unsigned bytes, unsigned mbar) {
    asm volatile(
        "cp.async.bulk.shared::cluster.global.mbarrier::complete_tx::bytes "
        "[%0], [%1], %2, [%3];"
        :: "r"(dst_smem), "l"(src), "r"(bytes), "r"(mbar) : "memory");
}

// ---------------------------------------------------------------------------
// Kernel 1 (fused): scores + raw-score write + memories copy + flash-style
// unnormalized weighted accumulation, all in one streaming pass.
// Grid (8 chunks of 1024 slots, 64 units) = 512 blocks, 256 threads.
// Per stage (32 slots): each of 8 warps handles 4 slots. Per slot:
//   dot via 32xfloat2 LDS.64 + 5-shuffle reduce (result uniform in warp),
//   mask -> -1e9, * 1/tmpr, raw-score STG (lane==j),
//   online (mx, se) update + accumulator rescale (uniform per warp),
//   acc += e * mem_row (lane's float2), copy STG.64 of mem_row.
// ---------------------------------------------------------------------------
__global__ void __launch_bounds__(256)
k_fused(const float* __restrict__ att,
        const float* __restrict__ atts,
        const float* __restrict__ mem,
        const int*   __restrict__ mask,
        const float* __restrict__ tmpr,
        float*       __restrict__ w_out,      // raw scores
        float*       __restrict__ mem_copy)
{
    __shared__ __align__(128) float4 stg_att[NSTAGES][STAGE_SLOTS * 16]; // 24 KB
    __shared__ __align__(128) float4 stg_mem[NSTAGES][STAGE_SLOTS * 16]; // 24 KB
    __shared__ int    msk[SLOTS_PER_CHUNK];                              // 4 KB
    __shared__ float2 waccs[8][33];                                      // padded
    __shared__ float2 wstat[8];
    __shared__ __align__(8) unsigned long long mbar[NSTAGES];

    int u     = blockIdx.y;
    int chunk = blockIdx.x;
    int m0    = chunk * SLOTS_PER_CHUNK;
    int tid   = threadIdx.x;
    int warp  = tid >> 5;
    int lane  = tid & 31;

    float2 q = ((const float2*)(att + (u << 6)))[lane];   // query float2
    float  inv_t = 1.0f / tmpr[u];

    const char* gatt = (const char*)(atts + ((size_t)u << 19) + ((size_t)m0 << 6));
    const char* gmem = (const char*)(mem  + ((size_t)u << 19) + ((size_t)m0 << 6));
    float*      wrow = w_out + ((size_t)u << 13) + m0;
    const int*  mrow = mask  + ((size_t)u << 13) + m0;
    float2*     dst  = (float2*)(mem_copy + ((size_t)u << 19) + ((size_t)m0 << 6));

    if (tid == 0) {
        #pragma unroll
        for (int i = 0; i < NSTAGES; i++) mbar_init(smem_u32(&mbar[i]), 1);
    }
    // Preload mask chunk into smem (coalesced)
    #pragma unroll
    for (int j = 0; j < SLOTS_PER_CHUNK / 256; j++)
        msk[tid + j * 256] = mrow[tid + j * 256];
    __syncthreads();

    if (tid == 0) {
        #pragma unroll
        for (int p = 0; p < NSTAGES; p++) {
            unsigned mb = smem_u32(&mbar[p]);
            mbar_expect_tx(mb, ATT_STAGE_BYTES + MEM_STAGE_BYTES);
            bulk_load(smem_u32(&stg_att[p][0]), gatt + (size_t)p * ATT_STAGE_BYTES,
                      ATT_STAGE_BYTES, mb);
            bulk_load(smem_u32(&stg_mem[p][0]), gmem + (size_t)p * MEM_STAGE_BYTES,
                      MEM_STAGE_BYTES, mb);
        }
    }

    float  mx  = -3.4e38f;          // per-warp online stats (uniform in warp)
    float  se  = 0.f;
    float2 acc = make_float2(0.f, 0.f);

    int buf = 0, ph = 0;
    for (int s = 0; s < NITERS; s++) {
        mbar_wait(smem_u32(&mbar[buf]), ph);

        #pragma unroll
        for (int j = 0; j < 4; j++) {
            int sl = warp * 4 + j;                 // slot within stage
            int m  = s * STAGE_SLOTS + sl;         // slot within chunk
            float2 a = ((const float2*)&stg_att[buf][sl * 16])[lane];
            float sv = a.x * q.x + a.y * q.y;
            #pragma unroll
            for (int o = 16; o > 0; o >>= 1)
                sv += __shfl_xor_sync(0xffffffffu, sv, o);
            if (msk[m]) sv = -1e9f;                // RandomMask before temperature
            sv *= inv_t;
            if (lane == j) __stcg(&wrow[m], sv);   // raw score (normalized in K2)

            float2 v = ((const float2*)&stg_mem[buf][sl * 16])[lane];
            float nm = fmaxf(mx, sv);
            float f  = __expf(mx - nm);
            float e  = __expf(sv - nm);
            acc.x = acc.x * f + e * v.x;
            acc.y = acc.y * f + e * v.y;
            se    = se * f + e;
            mx    = nm;
            __stcs(&dst[(size_t)m * 32 + lane], v);   // fused memories copy
        }

        __syncthreads();      // all consumers done with buf
        if (tid == 0 && s + NSTAGES < NITERS) {
            unsigned mb = smem_u32(&mbar[buf]);
            mbar_expect_tx(mb, ATT_STAGE_BYTES + MEM_STAGE_BYTES);
            bulk_load(smem_u32(&stg_att[buf][0]),
                      gatt + (size_t)(s + NSTAGES) * ATT_STAGE_BYTES,
                      ATT_STAGE_BYTES, mb);
            bulk_load(smem_u32(&stg_mem[buf][0]),
                      gmem + (size_t)(s + NSTAGES) * MEM_STAGE_BYTES,
                      MEM_STAGE_BYTES, mb);
        }
        if (++buf == NSTAGES) { buf = 0; ph ^= 1; }
    }

    // Block combine (deterministic): 8 warp-accumulators -> chunk partial
    waccs[warp][lane] = acc;
    if (lane == 0) wstat[warp] = make_float2(mx, se);
    __syncthreads();

    if (tid < 64) {
        float mxb = wstat[0].x;
        #pragma unroll
        for (int wi = 1; wi < 8; wi++) mxb = fmaxf(mxb, wstat[wi].x);
        float o = 0.f;
        int   c = tid >> 1;           // lane index in warp acc
        #pragma unroll
        for (int wi = 0; wi < 8; wi++) {
            float sc = __expf(wstat[wi].x - mxb);
            float2 a2 = waccs[wi][c];
            o += ((tid & 1) ? a2.y : a2.x) * sc;
        }
        g_partial[((size_t)u * CHUNKS + chunk) * 64 + tid] = o;
        if (tid == 0) {
            float seb = 0.f;
            #pragma unroll
            for (int wi = 0; wi < 8; wi++)
                seb += wstat[wi].y * __expf(wstat[wi].x - mxb);
            g_stats[u * CHUNKS + chunk] = make_float2(mxb, seb);
        }
    }
}

// ---------------------------------------------------------------------------
// Kernel 2 (finalize): per unit, combine 8 chunk stats/partials -> outputs;
// normalize raw weights (L2-resident 2 MB). Grid 64, 256 threads.
// ---------------------------------------------------------------------------
__global__ void __launch_bounds__(256)
k_finalize(float* __restrict__ w,            // raw in, normalized out
           float* __restrict__ outputs)
{
    __shared__ float s_mx, s_inv, s_scale[CHUNKS];

    int u   = blockIdx.x;
    int tid = threadIdx.x;

    if (tid == 0) {
        float mxu = g_stats[u * CHUNKS].x;
        #pragma unroll
        for (int c = 1; c < CHUNKS; c++)
            mxu = fmaxf(mxu, g_stats[u * CHUNKS + c].x);
        float seu = 0.f;
        #pragma unroll
        for (int c = 0; c < CHUNKS; c++) {
            float sc = __expf(g_stats[u * CHUNKS + c].x - mxu);
            s_scale[c] = sc;
            seu += g_stats[u * CHUNKS + c].y * sc;
        }
        s_mx  = mxu;
        s_inv = 1.0f / seu;
    }
    __syncthreads();

    float mxu = s_mx;
    float inv = s_inv;

    if (tid < 64) {
        float o = 0.f;
        #pragma unroll
        for (int c = 0; c < CHUNKS; c++)
            o += g_partial[((size_t)u * CHUNKS + c) * 64 + tid] * s_scale[c];
        outputs[(u << 6) + tid] = o * inv;
    }

    // Normalize weights: 8192 floats = 2048 float4; 8 per thread
    float4* wr = (float4*)(w + ((size_t)u << 13));
    #pragma unroll
    for (int j = 0; j < 8; j++) {
        int idx = tid + j * 256;
        float4 x = wr[idx];
        x.x = __expf(x.x - mxu) * inv;
        x.y = __expf(x.y - mxu) * inv;
        x.z = __expf(x.z - mxu) * inv;
        x.w = __expf(x.w - mxu) * inv;
        wr[idx] = x;
    }
}

// ---------------------------------------------------------------------------
extern "C" void kernel_launch(void* const* d_in, const int* in_sizes, int n_in,
                              void* d_out, int out_size)
{
    const float* att  = (const float*)d_in[0];   // [64,64]
    const float* atts = (const float*)d_in[1];   // [64,8192,64]
    const float* mem  = (const float*)d_in[2];   // [64,8192,64]
    const float* tmpr = (const float*)d_in[3];   // [64,1]
    const int*   mask = (const int*)  d_in[4];   // [64,8192] bool->int32

    float* out      = (float*)d_out;
    float* outputs  = out + OFF_OUTPUTS;
    float* weights  = out + OFF_WEIGHTS;
    float* mem_copy = out + OFF_MEMCOPY;

    // 1) fused: scores + copy + flash-style accumulation (single wave)
    {
        dim3 grid(CHUNKS, U);
        k_fused<<<grid, 256>>>(att, atts, mem, mask, tmpr, weights, mem_copy);
    }
    // 2) finalize: combine partials + normalize weights (all L2-resident)
    k_finalize<<<U, 256>>>(weights, outputs);
}

// round 13
// speedup vs baseline: 1.0004x; 1.0004x over previous
#include <cuda_runtime.h>
#include <math.h>

// Problem constants
#define U 64
#define M 8192
#define D 64
#define CHUNKS 8                        // 8 chunks x 64 units = 512 blocks (1 wave)
#define SLOTS_PER_CHUNK (M / CHUNKS)    // 1024

// Fused pipeline: 32 slots/stage; att 8 KB + mem 8 KB per stage; 3 stages
#define STAGE_SLOTS 32
#define ATT_STAGE_BYTES (STAGE_SLOTS * D * 4)     // 8192
#define MEM_STAGE_BYTES (STAGE_SLOTS * D * 4)     // 8192
#define NSTAGES 3
#define NITERS (SLOTS_PER_CHUNK / STAGE_SLOTS)    // 32

// Output layout (float32, tuple concatenated):
//   outputs  [64,64]      at 0
//   weights  [64,8192]    at 4096
//   memories [64,8192,64] at 528384
#define OFF_OUTPUTS  0
#define OFF_WEIGHTS  (U * D)
#define OFF_MEMCOPY  (U * D + U * M)

// Scratch (device globals; no allocation, no cross-block sync needed)
__device__ float2 g_stats[U * CHUNKS];           // per-(unit,chunk) (max, sumexp)
__device__ float  g_partial[U * CHUNKS * D];     // per-(unit,chunk) partial outputs

// ---------------------------------------------------------------------------
// mbarrier / bulk-async helpers
// ---------------------------------------------------------------------------
__device__ __forceinline__ unsigned smem_u32(const void* p) {
    return (unsigned)__cvta_generic_to_shared(p);
}
__device__ __forceinline__ void mbar_init(unsigned a, unsigned cnt) {
    asm volatile("mbarrier.init.shared.b64 [%0], %1;" :: "r"(a), "r"(cnt) : "memory");
}
__device__ __forceinline__ void mbar_expect_tx(unsigned a, unsigned bytes) {
    asm volatile("mbarrier.arrive.expect_tx.shared.b64 _, [%0], %1;"
                 :: "r"(a), "r"(bytes) : "memory");
}
__device__ __forceinline__ void mbar_wait(unsigned a, unsigned parity) {
    asm volatile(
        "{\n\t.reg .pred p;\n\t"
        "WL_%=:\n\t"
        "mbarrier.try_wait.parity.acquire.cta.shared::cta.b64 p, [%0], %1, 0x989680;\n\t"
        "@!p bra WL_%=;\n\t}"
        :: "r"(a), "r"(parity) : "memory");
}
__device__ __forceinline__ void bulk_load(unsigned dst_smem, const void* src,
                                          unsigned bytes, unsigned mbar) {
    asm volatile(
        "cp.async.bulk.shared::cluster.global.mbarrier::complete_tx::bytes "
        "[%0], [%1], %2, [%3];"
        :: "r"(dst_smem), "l"(src), "r"(bytes), "r"(mbar) : "memory");
}

// ---------------------------------------------------------------------------
// Kernel 1 (fused): scores + raw-score write + memories copy + flash-style
// unnormalized weighted accumulation, all in one streaming pass.
// Grid (8 chunks of 1024 slots, 64 units) = 512 blocks, 256 threads.
// (Byte-identical to R10's k_fused.)
// ---------------------------------------------------------------------------
__global__ void __launch_bounds__(256)
k_fused(const float* __restrict__ att,
        const float* __restrict__ atts,
        const float* __restrict__ mem,
        const int*   __restrict__ mask,
        const float* __restrict__ tmpr,
        float*       __restrict__ w_out,      // raw scores
        float*       __restrict__ mem_copy)
{
    __shared__ __align__(128) float4 stg_att[NSTAGES][STAGE_SLOTS * 16]; // 24 KB
    __shared__ __align__(128) float4 stg_mem[NSTAGES][STAGE_SLOTS * 16]; // 24 KB
    __shared__ int    msk[SLOTS_PER_CHUNK];                              // 4 KB
    __shared__ float2 waccs[8][33];                                      // padded
    __shared__ float2 wstat[8];
    __shared__ __align__(8) unsigned long long mbar[NSTAGES];

    int u     = blockIdx.y;
    int chunk = blockIdx.x;
    int m0    = chunk * SLOTS_PER_CHUNK;
    int tid   = threadIdx.x;
    int warp  = tid >> 5;
    int lane  = tid & 31;

    float2 q = ((const float2*)(att + (u << 6)))[lane];   // query float2
    float  inv_t = 1.0f / tmpr[u];

    const char* gatt = (const char*)(atts + ((size_t)u << 19) + ((size_t)m0 << 6));
    const char* gmem = (const char*)(mem  + ((size_t)u << 19) + ((size_t)m0 << 6));
    float*      wrow = w_out + ((size_t)u << 13) + m0;
    const int*  mrow = mask  + ((size_t)u << 13) + m0;
    float2*     dst  = (float2*)(mem_copy + ((size_t)u << 19) + ((size_t)m0 << 6));

    if (tid == 0) {
        #pragma unroll
        for (int i = 0; i < NSTAGES; i++) mbar_init(smem_u32(&mbar[i]), 1);
    }
    // Preload mask chunk into smem (coalesced)
    #pragma unroll
    for (int j = 0; j < SLOTS_PER_CHUNK / 256; j++)
        msk[tid + j * 256] = mrow[tid + j * 256];
    __syncthreads();

    if (tid == 0) {
        #pragma unroll
        for (int p = 0; p < NSTAGES; p++) {
            unsigned mb = smem_u32(&mbar[p]);
            mbar_expect_tx(mb, ATT_STAGE_BYTES + MEM_STAGE_BYTES);
            bulk_load(smem_u32(&stg_att[p][0]), gatt + (size_t)p * ATT_STAGE_BYTES,
                      ATT_STAGE_BYTES, mb);
            bulk_load(smem_u32(&stg_mem[p][0]), gmem + (size_t)p * MEM_STAGE_BYTES,
                      MEM_STAGE_BYTES, mb);
        }
    }

    float  mx  = -3.4e38f;          // per-warp online stats (uniform in warp)
    float  se  = 0.f;
    float2 acc = make_float2(0.f, 0.f);

    int buf = 0, ph = 0;
    for (int s = 0; s < NITERS; s++) {
        mbar_wait(smem_u32(&mbar[buf]), ph);

        #pragma unroll
        for (int j = 0; j < 4; j++) {
            int sl = warp * 4 + j;                 // slot within stage
            int m  = s * STAGE_SLOTS + sl;         // slot within chunk
            float2 a = ((const float2*)&stg_att[buf][sl * 16])[lane];
            float sv = a.x * q.x + a.y * q.y;
            #pragma unroll
            for (int o = 16; o > 0; o >>= 1)
                sv += __shfl_xor_sync(0xffffffffu, sv, o);
            if (msk[m]) sv = -1e9f;                // RandomMask before temperature
            sv *= inv_t;
            if (lane == j) __stcg(&wrow[m], sv);   // raw score (normalized in K2)

            float2 v = ((const float2*)&stg_mem[buf][sl * 16])[lane];
            float nm = fmaxf(mx, sv);
            float f  = __expf(mx - nm);
            float e  = __expf(sv - nm);
            acc.x = acc.x * f + e * v.x;
            acc.y = acc.y * f + e * v.y;
            se    = se * f + e;
            mx    = nm;
            __stcs(&dst[(size_t)m * 32 + lane], v);   // fused memories copy
        }

        __syncthreads();      // all consumers done with buf
        if (tid == 0 && s + NSTAGES < NITERS) {
            unsigned mb = smem_u32(&mbar[buf]);
            mbar_expect_tx(mb, ATT_STAGE_BYTES + MEM_STAGE_BYTES);
            bulk_load(smem_u32(&stg_att[buf][0]),
                      gatt + (size_t)(s + NSTAGES) * ATT_STAGE_BYTES,
                      ATT_STAGE_BYTES, mb);
            bulk_load(smem_u32(&stg_mem[buf][0]),
                      gmem + (size_t)(s + NSTAGES) * MEM_STAGE_BYTES,
                      MEM_STAGE_BYTES, mb);
        }
        if (++buf == NSTAGES) { buf = 0; ph ^= 1; }
    }

    // Block combine (deterministic): 8 warp-accumulators -> chunk partial
    waccs[warp][lane] = acc;
    if (lane == 0) wstat[warp] = make_float2(mx, se);
    __syncthreads();

    if (tid < 64) {
        float mxb = wstat[0].x;
        #pragma unroll
        for (int wi = 1; wi < 8; wi++) mxb = fmaxf(mxb, wstat[wi].x);
        float o = 0.f;
        int   c = tid >> 1;           // lane index in warp acc
        #pragma unroll
        for (int wi = 0; wi < 8; wi++) {
            float sc = __expf(wstat[wi].x - mxb);
            float2 a2 = waccs[wi][c];
            o += ((tid & 1) ? a2.y : a2.x) * sc;
        }
        g_partial[((size_t)u * CHUNKS + chunk) * 64 + tid] = o;
        if (tid == 0) {
            float seb = 0.f;
            #pragma unroll
            for (int wi = 0; wi < 8; wi++)
                seb += wstat[wi].y * __expf(wstat[wi].x - mxb);
            g_stats[u * CHUNKS + chunk] = make_float2(mxb, seb);
        }
    }
}

// ---------------------------------------------------------------------------
// Kernel 2 (finalize): grid (CHUNKS+1, U) = 576 blocks, 256 threads.
// Every block redundantly derives (max_u, inv_sum_u, scales) from g_stats in
// fixed order (bit-identical). Blocks 0..7 normalize their 1024-weight slice
// (1 float4 per thread). Block 8 combines the 8 chunk partials -> outputs.
// ---------------------------------------------------------------------------
__global__ void __launch_bounds__(256)
k_finalize(float* __restrict__ w,            // raw in, normalized out
           float* __restrict__ outputs)
{
    __shared__ float s_mx, s_inv, s_scale[CHUNKS];

    int u    = blockIdx.y;
    int part = blockIdx.x;     // 0..CHUNKS (CHUNKS = outputs block)
    int tid  = threadIdx.x;

    if (tid == 0) {
        float mxu = g_stats[u * CHUNKS].x;
        #pragma unroll
        for (int c = 1; c < CHUNKS; c++)
            mxu = fmaxf(mxu, g_stats[u * CHUNKS + c].x);
        float seu = 0.f;
        #pragma unroll
        for (int c = 0; c < CHUNKS; c++) {
            float sc = __expf(g_stats[u * CHUNKS + c].x - mxu);
            s_scale[c] = sc;
            seu += g_stats[u * CHUNKS + c].y * sc;
        }
        s_mx  = mxu;
        s_inv = 1.0f / seu;
    }
    __syncthreads();

    float mxu = s_mx;
    float inv = s_inv;

    if (part < CHUNKS) {
        // Normalize this block's 1024-weight slice: 256 float4, 1 per thread
        float4* wr = (float4*)(w + ((size_t)u << 13) + part * SLOTS_PER_CHUNK);
        float4 x = wr[tid];
        x.x = __expf(x.x - mxu) * inv;
        x.y = __expf(x.y - mxu) * inv;
        x.z = __expf(x.z - mxu) * inv;
        x.w = __expf(x.w - mxu) * inv;
        wr[tid] = x;
    } else {
        if (tid < 64) {
            float o = 0.f;
            #pragma unroll
            for (int c = 0; c < CHUNKS; c++)
                o += g_partial[((size_t)u * CHUNKS + c) * 64 + tid] * s_scale[c];
            outputs[(u << 6) + tid] = o * inv;
        }
    }
}

// ---------------------------------------------------------------------------
extern "C" void kernel_launch(void* const* d_in, const int* in_sizes, int n_in,
                              void* d_out, int out_size)
{
    const float* att  = (const float*)d_in[0];   // [64,64]
    const float* atts = (const float*)d_in[1];   // [64,8192,64]
    const float* mem  = (const float*)d_in[2];   // [64,8192,64]
    const float* tmpr = (const float*)d_in[3];   // [64,1]
    const int*   mask = (const int*)  d_in[4];   // [64,8192] bool->int32

    float* out      = (float*)d_out;
    float* outputs  = out + OFF_OUTPUTS;
    float* weights  = out + OFF_WEIGHTS;
    float* mem_copy = out + OFF_MEMCOPY;

    // 1) fused: scores + copy + flash-style accumulation (single wave)
    {
        dim3 grid(CHUNKS, U);
        k_fused<<<grid, 256>>>(att, atts, mem, mask, tmpr, weights, mem_copy);
    }
    // 2) finalize: parallel weights normalization + outputs combine
    {
        dim3 grid(CHUNKS + 1, U);
        k_finalize<<<grid, 256>>>(weights, outputs);
    }
}